// round 16
// baseline (speedup 1.0000x reference)
#include <cuda_runtime.h>
#include <cuda_fp16.h>
#include <cuda_bf16.h>
#include <cstdint>

#define NN 50000
#define NE 800000
#define F  128

// ---------------- scratch (static device globals; zero-initialized at load) -----
__device__ __align__(16) int    g_deg[NN];      // re-zeroed by scan_kernel each call
__device__ __align__(16) int    g_cursor[NN];   // re-zeroed by edge_kernel each call
__device__ __align__(16) int    g_rowptr[NN + 1];
__device__ __align__(16) int    g_csrc[NE];
__device__ __align__(16) __half g_ABh[(size_t)NN * 256];
__device__ __align__(16) int    g_bsum[64];
__device__ __align__(16) int    g_boff[64];
__device__ int g_is64;
__device__ int g_scan_ctr;                      // reset by scan_kernel's last block

// fp16 activation tables (exact GEMM A operands)
__device__ __align__(16) __half g_x16[NN * F];
__device__ __align__(16) __half g_m16[NN * F];
__device__ __align__(16) __half g_h1h16[NN * F];
__device__ __align__(16) __half g_h2h16[NN * F];
// weights transposed + fp16 hi/lo split: wt[n][k];
// wt1 @0 (K=256), wt2 @32768 (K=256), wtc @65536 (two 128x128 halves, +by*16384)
__device__ __align__(16) __half g_wt_hi[98304], g_wt_lo[98304];

// ---------------- helpers -----------------------------------------------------
__device__ __forceinline__ uint32_t sm32(const void* p) {
    uint32_t a;
    asm("{ .reg .u64 t; cvta.to.shared.u64 t, %1; cvt.u32.u64 %0, t; }"
        : "=r"(a) : "l"(p));
    return a;
}

__device__ __forceinline__ void ldm_x4(uint32_t (&r)[4], uint32_t addr) {
    asm volatile("ldmatrix.sync.aligned.m8n8.x4.shared.b16 {%0,%1,%2,%3}, [%4];"
        : "=r"(r[0]), "=r"(r[1]), "=r"(r[2]), "=r"(r[3]) : "r"(addr));
}
__device__ __forceinline__ void ldm_x2(uint32_t (&r)[2], uint32_t addr) {
    asm volatile("ldmatrix.sync.aligned.m8n8.x2.shared.b16 {%0,%1}, [%2];"
        : "=r"(r[0]), "=r"(r[1]) : "r"(addr));
}
// fp16 x fp16 -> fp32 MMA
__device__ __forceinline__ void mma16816h(float (&d)[4], const uint32_t (&a)[4],
                                          const uint32_t (&b)[2]) {
    asm volatile("mma.sync.aligned.m16n8k16.row.col.f32.f16.f16.f32 "
        "{%0,%1,%2,%3}, {%4,%5,%6,%7}, {%8,%9}, {%0,%1,%2,%3};"
        : "+f"(d[0]), "+f"(d[1]), "+f"(d[2]), "+f"(d[3])
        : "r"(a[0]), "r"(a[1]), "r"(a[2]), "r"(a[3]), "r"(b[0]), "r"(b[1]));
}

// final rowptr with folded block offset
__device__ __forceinline__ int rp(int i) {
    return (i >= NN) ? NE : g_rowptr[i] + g_boff[i >> 10];
}

// ---------------- index dtype detection + decode ---------------------------------
__device__ __forceinline__ int detect64(const void* p) {
    const int* w = (const int*)p;
    int is64 = 1;
#pragma unroll
    for (int i = 1; i < 32; i += 2)
        if (w[i] != 0) is64 = 0;
    return is64;
}

__device__ __forceinline__ int load_idx_raw(const void* p, long long pos, int is64) {
    int v;
    if (is64) v = (int)((const long long*)p)[pos];
    else      v = ((const int*)p)[pos];
    return min(max(v, 0), NN - 1);
}
__device__ __forceinline__ int load_idx(const void* p, long long pos) {
    return load_idx_raw(p, pos, g_is64);
}

// ---------------- fused setup: detect + weight prep + x convert + HIST ----------
__global__ void setup_kernel(const void* __restrict__ eidx,
                             const float* __restrict__ x,
                             const float* __restrict__ W1l, const float* __restrict__ W1r,
                             const float* __restrict__ W2l, const float* __restrict__ W2r,
                             const float* __restrict__ Wc1)
{
    long long gid = (long long)blockIdx.x * blockDim.x + threadIdx.x;
    if (gid == 0) g_is64 = detect64(eidx);

    if (gid < 98304) {
        long long wI = gid;
        float v;
        if (wI < 32768) {
            int n = (int)(wI >> 8), k = (int)(wI & 255);
            v = (k < 128) ? W1l[k * 128 + n] : W1r[(k - 128) * 128 + n];
        } else if (wI < 65536) {
            long long l = wI - 32768;
            int n = (int)(l >> 8), k = (int)(l & 255);
            v = (k < 128) ? W2l[k * 128 + n] : W2r[(k - 128) * 128 + n];
        } else {
            long long l = wI - 65536;
            int by = (int)(l >> 14), r = (int)(l & 16383);
            int n = r >> 7, k = r & 127;
            v = Wc1[(size_t)(by * 128 + k) * 128 + n];
        }
        __half h = __float2half_rn(v);
        g_wt_hi[wI] = h;
        g_wt_lo[wI] = __float2half_rn(v - __half2float(h));
    }

    long long cI = gid - 98304;
    if (cI >= 0 && cI < (long long)NN * 32) {
        float4 v = *(const float4*)(x + cI * 4);
        __half2 f01 = __floats2half2_rn(v.x, v.y);
        __half2 f23 = __floats2half2_rn(v.z, v.w);
        uint2 pk;
        pk.x = *(unsigned*)&f01;
        pk.y = *(unsigned*)&f23;
        *(uint2*)(g_x16 + cI * 4) = pk;
    }

    long long hI = gid - 98304 - (long long)NN * 32;
    if (hI >= 0 && hI < NE) {
        int is64 = detect64(eidx);
        int d = load_idx_raw(eidx, (long long)NE + hI, is64);
        atomicAdd(&g_deg[d], 1);
    }
}

// ---------------- per-block scan with fused cross-block scan ---------------------
__global__ void scan_kernel() {
    __shared__ int warp_sums[32];
    __shared__ int sLast;
    __shared__ int sh[64];
    int b = blockIdx.x, t = threadIdx.x;
    int i = b * 1024 + t;
    int lane = t & 31, w = t >> 5;
    int v = (i < NN) ? g_deg[i] : 0;
    if (i < NN) g_deg[i] = 0;
    int s = v;
#pragma unroll
    for (int off = 1; off < 32; off <<= 1) {
        int n = __shfl_up_sync(0xFFFFFFFFu, s, off);
        if (lane >= off) s += n;
    }
    if (lane == 31) warp_sums[w] = s;
    __syncthreads();
    if (w == 0) {
        int ws = warp_sums[lane];
#pragma unroll
        for (int off = 1; off < 32; off <<= 1) {
            int n = __shfl_up_sync(0xFFFFFFFFu, ws, off);
            if (lane >= off) ws += n;
        }
        warp_sums[lane] = ws;
    }
    __syncthreads();
    int woff = (w == 0) ? 0 : warp_sums[w - 1];
    int incl = s + woff;
    if (i < NN) g_rowptr[i] = incl - v;
    if (t == 1023) g_bsum[b] = incl;

    __threadfence();
    if (t == 0) sLast = (atomicAdd(&g_scan_ctr, 1) == (int)gridDim.x - 1);
    __syncthreads();
    if (sLast) {
        __threadfence();
        if (t < 64) sh[t] = (t < (int)gridDim.x) ? g_bsum[t] : 0;
        __syncthreads();
        for (int off = 1; off < 64; off <<= 1) {
            int n = (t < 64 && t >= off) ? sh[t - off] : 0;
            __syncthreads();
            if (t < 64) sh[t] += n;
            __syncthreads();
        }
        if (t < 64) {
            int bv = (t < (int)gridDim.x) ? g_bsum[t] : 0;
            g_boff[t] = sh[t] - bv;
        }
        if (t == 0) { g_rowptr[NN] = NE; g_scan_ctr = 0; }
    }
}

__global__ void scatter_kernel(const void* __restrict__ eidx) {
    int e = blockIdx.x * blockDim.x + threadIdx.x;
    if (e < NE) {
        int d = load_idx(eidx, (long long)NE + e);
        int pos = rp(d) + atomicAdd(&g_cursor[d], 1);
        if (pos >= 0 && pos < NE) g_csrc[pos] = load_idx(eidx, e);
    }
}

// ---------------- segment mean: half-warp per neighbor, uint4 loads --------------
// lanes 0-15 handle even neighbors, 16-31 odd; each lane covers 8 channels.
template <int WHICH>   // 0: gather g_x16, 1: gather g_h1h16
__global__ void aggregate_kernel() {
    const __half* __restrict__ p = (WHICH == 0) ? g_x16 : g_h1h16;
    int gw   = (blockIdx.x * blockDim.x + threadIdx.x) >> 5;
    int lane = threadIdx.x & 31;
    if (gw >= NN) return;
    int hf = lane >> 4;         // 0 or 1
    int hl = lane & 15;         // 0..15
    int j  = hl * 8;            // channel base (8 channels per lane)

    int r0 = rp(gw);
    int r1 = rp(gw + 1);

    float acc[8];
#pragma unroll
    for (int c = 0; c < 8; c++) acc[c] = 0.f;

    for (int i = r0 + hf; i < r1; i += 2) {
        int s = g_csrc[i];
        uint4 v = *(const uint4*)(p + (size_t)s * F + j);
        float2 f0 = __half22float2(*(__half2*)&v.x);
        float2 f1 = __half22float2(*(__half2*)&v.y);
        float2 f2 = __half22float2(*(__half2*)&v.z);
        float2 f3 = __half22float2(*(__half2*)&v.w);
        acc[0] += f0.x; acc[1] += f0.y;
        acc[2] += f1.x; acc[3] += f1.y;
        acc[4] += f2.x; acc[5] += f2.y;
        acc[6] += f3.x; acc[7] += f3.y;
    }
    // combine odd-half into even-half
#pragma unroll
    for (int c = 0; c < 8; c++)
        acc[c] += __shfl_down_sync(0xFFFFFFFFu, acc[c], 16);

    if (hf == 0) {
        float inv = 1.0f / (float)max(r1 - r0, 1);
        __half2 h0 = __floats2half2_rn(acc[0] * inv, acc[1] * inv);
        __half2 h1 = __floats2half2_rn(acc[2] * inv, acc[3] * inv);
        __half2 h2 = __floats2half2_rn(acc[4] * inv, acc[5] * inv);
        __half2 h3 = __floats2half2_rn(acc[6] * inv, acc[7] * inv);
        uint4 pk;
        pk.x = *(unsigned*)&h0;
        pk.y = *(unsigned*)&h1;
        pk.z = *(unsigned*)&h2;
        pk.w = *(unsigned*)&h3;
        *(uint4*)(g_m16 + (size_t)gw * F + j) = pk;
    }
}

// ---------------- HMMA fp16 GEMM: 64x128 tile, 256 threads ------------------------
// MODE 0: h1 = relu(mean@W1 + x@W1r + b)  -> g_h1h16 fp16, K=256
// MODE 1: h2 = mean@W2 + h1@W2r + b       -> g_h2h16 fp16, K=256
// MODE 2: ABh[:, by*128..] = h2 @ wtc_by  -> g_ABh fp16, K=128, grid.y=2
#define SAPAD 40
#define BMT 64

template <int MODE>
__global__ __launch_bounds__(256)
void mma_gemm(const float* __restrict__ bias, int M)
{
    constexpr int NCHUNK = (MODE <= 1) ? 8 : 4;
    constexpr int KTOT   = (MODE <= 1) ? 256 : 128;
    const int wtoff = (MODE == 0) ? 0 : (MODE == 1) ? 32768
                     : 65536 + (int)blockIdx.y * 16384;

    __shared__ __half sA[BMT][SAPAD];
    __shared__ __half sWh[128][SAPAD], sWl[128][SAPAD];

    int tid  = threadIdx.x;
    int wid  = tid >> 5, lane = tid & 31;
    int m0   = blockIdx.x * BMT;
    int wm   = wid >> 2, wn = wid & 3;
    int mb   = wm * 32,  nb = wn * 32;

    float acc[2][4][4];
#pragma unroll
    for (int mi = 0; mi < 2; mi++)
#pragma unroll
        for (int ni = 0; ni < 4; ni++)
#pragma unroll
            for (int q = 0; q < 4; q++) acc[mi][ni][q] = 0.f;

    const int farow = tid >> 2;
    const int fseg  = (tid & 3) * 8;
    const int gmf   = m0 + farow;
    const int fwrow = tid >> 2;

    const int a_r = (lane & 15);
    const int a_c = (lane >> 4) * 8;
    const int b_r = (lane & 7);
    const int b_c = ((lane >> 3) & 1) * 8;

    for (int ch = 0; ch < NCHUNK; ch++) {
        const __half* a16;
        int kk0;
        if (MODE == 2)      { a16 = g_h2h16; kk0 = ch * 32; }
        else if (ch < 4)    { a16 = g_m16;   kk0 = ch * 32; }
        else if (MODE == 0) { a16 = g_x16;   kk0 = (ch - 4) * 32; }
        else                { a16 = g_h1h16; kk0 = (ch - 4) * 32; }
        int kkw = ch * 32;

        {
            uint4 va = make_uint4(0, 0, 0, 0);
            if (gmf < M) va = *(const uint4*)(a16 + (size_t)gmf * F + kk0 + fseg);
            *(uint4*)&sA[farow][fseg] = va;
            *(uint4*)&sWh[fwrow][fseg] =
                *(const uint4*)(g_wt_hi + wtoff + (size_t)fwrow * KTOT + kkw + fseg);
            *(uint4*)&sWh[fwrow + 64][fseg] =
                *(const uint4*)(g_wt_hi + wtoff + (size_t)(fwrow + 64) * KTOT + kkw + fseg);
            *(uint4*)&sWl[fwrow][fseg] =
                *(const uint4*)(g_wt_lo + wtoff + (size_t)fwrow * KTOT + kkw + fseg);
            *(uint4*)&sWl[fwrow + 64][fseg] =
                *(const uint4*)(g_wt_lo + wtoff + (size_t)(fwrow + 64) * KTOT + kkw + fseg);
        }
        __syncthreads();

#pragma unroll
        for (int ks = 0; ks < 2; ks++) {
            uint32_t af[2][4], whf[4][2], wlf[4][2];
#pragma unroll
            for (int mi = 0; mi < 2; mi++)
                ldm_x4(af[mi], sm32(&sA[mb + mi * 16 + a_r][ks * 16 + a_c]));
#pragma unroll
            for (int ni = 0; ni < 4; ni++) {
                ldm_x2(whf[ni], sm32(&sWh[nb + ni * 8 + b_r][ks * 16 + b_c]));
                ldm_x2(wlf[ni], sm32(&sWl[nb + ni * 8 + b_r][ks * 16 + b_c]));
            }
#pragma unroll
            for (int mi = 0; mi < 2; mi++)
#pragma unroll
                for (int ni = 0; ni < 4; ni++) {
                    mma16816h(acc[mi][ni], af[mi], whf[ni]);
                    mma16816h(acc[mi][ni], af[mi], wlf[ni]);
                }
        }
        __syncthreads();
    }

    const int trow = lane >> 2;
    const int tcol = (lane & 3) * 2;
#pragma unroll
    for (int mi = 0; mi < 2; mi++) {
#pragma unroll
        for (int half = 0; half < 2; half++) {
            int m = m0 + mb + mi * 16 + trow + half * 8;
            if (m >= M) continue;
#pragma unroll
            for (int ni = 0; ni < 4; ni++) {
                int col = nb + ni * 8 + tcol;
                float vx = acc[mi][ni][half * 2 + 0];
                float vy = acc[mi][ni][half * 2 + 1];
                if (MODE <= 1) { vx += bias[col]; vy += bias[col + 1]; }
                if (MODE == 0) { vx = fmaxf(vx, 0.f); vy = fmaxf(vy, 0.f); }
                __half2 h = __floats2half2_rn(vx, vy);
                if (MODE == 0) {
                    *(__half2*)(g_h1h16 + (size_t)m * F + col) = h;
                } else if (MODE == 1) {
                    *(__half2*)(g_h2h16 + (size_t)m * F + col) = h;
                } else {
                    *(__half2*)(g_ABh + (size_t)m * 256 + blockIdx.y * 128 + col) = h;
                }
            }
        }
    }
}

// ---------------- edge classifier: half-warp per edge, uint4 loads ----------------
__global__ __launch_bounds__(256)
void edge_kernel(const void* __restrict__ eidx,
                 const float* __restrict__ ea,
                 const float* __restrict__ Wc1,
                 const float* __restrict__ bc1,
                 const float* __restrict__ Wc2,
                 const float* __restrict__ bc2,
                 float* __restrict__ out)
{
    __shared__ float sWe0[128], sWe1[128], sWe2[128], sb[128], sw2[128];
    int tid = threadIdx.x;

    // recycle cursor for next graph replay (runs after scatter)
    int gth = blockIdx.x * blockDim.x + tid;
    if (gth < NN) g_cursor[gth] = 0;

    if (tid < 128) {
        sWe0[tid] = Wc1[256 * 128 + tid];
        sWe1[tid] = Wc1[257 * 128 + tid];
        sWe2[tid] = Wc1[258 * 128 + tid];
        sb[tid]   = bc1[tid];
        sw2[tid]  = Wc2[tid];
    }
    __syncthreads();

    int lane = tid & 31;
    int hf = lane >> 4;           // 0 or 1 (edge selector within warp)
    int hl = lane & 15;           // lane within half-warp
    long long e = ((long long)blockIdx.x * (blockDim.x >> 5) + (tid >> 5)) * 2 + hf;
    if (e >= NE) return;
    int j = hl * 8;               // 8 channels per lane

    int s = load_idx(eidx, e);
    int d = load_idx(eidx, (long long)NE + e);

    uint4 av = *(const uint4*)(g_ABh + (size_t)s * 256 + j);
    uint4 bv = *(const uint4*)(g_ABh + (size_t)d * 256 + 128 + j);

    float e0 = ea[(size_t)e * 3 + 0];
    float e1 = ea[(size_t)e * 3 + 1];
    float e2 = ea[(size_t)e * 3 + 2];

    float acc = 0.f;
#pragma unroll
    for (int q = 0; q < 4; q++) {
        unsigned au = (&av.x)[q];
        unsigned bu = (&bv.x)[q];
        float2 af = __half22float2(*(__half2*)&au);
        float2 bf = __half22float2(*(__half2*)&bu);
        int c = j + q * 2;
        float h;
        h = af.x + bf.x + e0 * sWe0[c] + e1 * sWe1[c] + e2 * sWe2[c] + sb[c];
        acc += fmaxf(h, 0.f) * sw2[c];
        h = af.y + bf.y + e0 * sWe0[c + 1] + e1 * sWe1[c + 1] + e2 * sWe2[c + 1] + sb[c + 1];
        acc += fmaxf(h, 0.f) * sw2[c + 1];
    }

    // reduce within 16-lane half-warp
#pragma unroll
    for (int off = 8; off > 0; off >>= 1)
        acc += __shfl_xor_sync(0xFFFFFFFFu, acc, off);

    if (hl == 0) out[e] = acc + bc2[0];
}

// ---------------- launch -----------------------------------------------------------
extern "C" void kernel_launch(void* const* d_in, const int* in_sizes, int n_in,
                              void* d_out, int out_size)
{
    const float* x    = (const float*)d_in[0];
    const void*  eidx = d_in[1];
    const float* ea   = (const float*)d_in[2];
    const float* W1l  = (const float*)d_in[3];
    const float* b1l  = (const float*)d_in[4];
    const float* W1r  = (const float*)d_in[5];
    const float* W2l  = (const float*)d_in[6];
    const float* b2l  = (const float*)d_in[7];
    const float* W2r  = (const float*)d_in[8];
    const float* Wc1  = (const float*)d_in[9];
    const float* bc1  = (const float*)d_in[10];
    const float* Wc2  = (const float*)d_in[11];
    const float* bc2  = (const float*)d_in[12];
    float* out = (float*)d_out;

    const int SCAN_BLOCKS = (NN + 1023) / 1024;  // 49

    long long setup_threads = 98304 + (long long)NN * 32 + NE;
    int setup_grid = (int)((setup_threads + 255) / 256);
    setup_kernel<<<setup_grid, 256>>>(eidx, x, W1l, W1r, W2l, W2r, Wc1);

    scan_kernel<<<SCAN_BLOCKS, 1024>>>();
    scatter_kernel<<<(NE + 255) / 256, 256>>>(eidx);

    const int aggGrid  = (NN * 32 + 255) / 256;
    const int gemmGrid = (NN + BMT - 1) / BMT;   // 782

    aggregate_kernel<0><<<aggGrid, 256>>>();
    mma_gemm<0><<<gemmGrid, 256>>>(b1l, NN);

    aggregate_kernel<1><<<aggGrid, 256>>>();
    mma_gemm<1><<<gemmGrid, 256>>>(b2l, NN);

    mma_gemm<2><<<dim3(gemmGrid, 2), 256>>>(nullptr, NN);

    // half-warp per edge: warps = NE/2, 8 warps per block
    const int edgeBlocks = (int)(((long long)NE / 2 + 7) / 8);
    edge_kernel<<<edgeBlocks, 256>>>(eidx, ea, Wc1, bc1, Wc2, bc2, out);
}

// round 17
// speedup vs baseline: 1.0810x; 1.0810x over previous
#include <cuda_runtime.h>
#include <cuda_fp16.h>
#include <cuda_bf16.h>
#include <cstdint>

#define NN 50000
#define NE 800000
#define F  128

// ---------------- scratch (static device globals) ---------------------------
__device__ __align__(16) int    g_deg[NN];
__device__ __align__(16) int    g_cursor[NN];
__device__ __align__(16) int    g_rowptr[NN + 1];   // block-local exclusive scan
__device__ __align__(16) int    g_csrc[NE];
__device__ __align__(16) __half g_ABh[(size_t)NN * 256];
__device__ __align__(16) int    g_bsum[64];
__device__ __align__(16) int    g_boff[64];
__device__ int g_is64;

// fp16 activation tables (exact GEMM A operands)
__device__ __align__(16) __half g_x16[NN * F];
__device__ __align__(16) __half g_m16[NN * F];
__device__ __align__(16) __half g_h1h16[NN * F];
__device__ __align__(16) __half g_h2h16[NN * F];
// weights transposed + fp16 hi/lo split: wt[n][k];
// wt1 @0 (K=256), wt2 @32768 (K=256), wtc @65536 (two 128x128 halves, +by*16384)
__device__ __align__(16) __half g_wt_hi[98304], g_wt_lo[98304];

// ---------------- helpers -----------------------------------------------------
__device__ __forceinline__ uint32_t sm32(const void* p) {
    uint32_t a;
    asm("{ .reg .u64 t; cvta.to.shared.u64 t, %1; cvt.u32.u64 %0, t; }"
        : "=r"(a) : "l"(p));
    return a;
}

__device__ __forceinline__ void ldm_x4(uint32_t (&r)[4], uint32_t addr) {
    asm volatile("ldmatrix.sync.aligned.m8n8.x4.shared.b16 {%0,%1,%2,%3}, [%4];"
        : "=r"(r[0]), "=r"(r[1]), "=r"(r[2]), "=r"(r[3]) : "r"(addr));
}
__device__ __forceinline__ void ldm_x2(uint32_t (&r)[2], uint32_t addr) {
    asm volatile("ldmatrix.sync.aligned.m8n8.x2.shared.b16 {%0,%1}, [%2];"
        : "=r"(r[0]), "=r"(r[1]) : "r"(addr));
}
// fp16 x fp16 -> fp32 MMA
__device__ __forceinline__ void mma16816h(float (&d)[4], const uint32_t (&a)[4],
                                          const uint32_t (&b)[2]) {
    asm volatile("mma.sync.aligned.m16n8k16.row.col.f32.f16.f16.f32 "
        "{%0,%1,%2,%3}, {%4,%5,%6,%7}, {%8,%9}, {%0,%1,%2,%3};"
        : "+f"(d[0]), "+f"(d[1]), "+f"(d[2]), "+f"(d[3])
        : "r"(a[0]), "r"(a[1]), "r"(a[2]), "r"(a[3]), "r"(b[0]), "r"(b[1]));
}

// final rowptr with folded block offset
__device__ __forceinline__ int rp(int i) {
    return (i >= NN) ? NE : g_rowptr[i] + g_boff[i >> 10];
}

// ---------------- index decode --------------------------------------------------
__device__ __forceinline__ int load_idx(const void* p, long long pos) {
    int v;
    if (g_is64) v = (int)((const long long*)p)[pos];
    else        v = ((const int*)p)[pos];
    return min(max(v, 0), NN - 1);
}

// ---------------- fused setup: detect + zero + weight prep + x convert ----------
__global__ void setup_kernel(const void* __restrict__ eidx,
                             const float* __restrict__ x,
                             const float* __restrict__ W1l, const float* __restrict__ W1r,
                             const float* __restrict__ W2l, const float* __restrict__ W2r,
                             const float* __restrict__ Wc1)
{
    long long gid = (long long)blockIdx.x * blockDim.x + threadIdx.x;
    if (gid == 0) {
        const int* w = (const int*)eidx;
        int is64 = 1;
        for (int i = 1; i < 256; i += 2)
            if (w[i] != 0) { is64 = 0; break; }
        g_is64 = is64;
    }
    if (gid < NN) { g_deg[gid] = 0; g_cursor[gid] = 0; }

    long long wI = gid - NN;
    if (wI >= 0 && wI < 98304) {
        float v;
        if (wI < 32768) {
            int n = (int)(wI >> 8), k = (int)(wI & 255);
            v = (k < 128) ? W1l[k * 128 + n] : W1r[(k - 128) * 128 + n];
        } else if (wI < 65536) {
            long long l = wI - 32768;
            int n = (int)(l >> 8), k = (int)(l & 255);
            v = (k < 128) ? W2l[k * 128 + n] : W2r[(k - 128) * 128 + n];
        } else {
            long long l = wI - 65536;
            int by = (int)(l >> 14), r = (int)(l & 16383);
            int n = r >> 7, k = r & 127;
            v = Wc1[(size_t)(by * 128 + k) * 128 + n];
        }
        __half h = __float2half_rn(v);
        g_wt_hi[wI] = h;
        g_wt_lo[wI] = __float2half_rn(v - __half2float(h));
    }

    long long cI = gid - NN - 98304;   // x convert: one float4 per thread
    if (cI >= 0 && cI < (long long)NN * 32) {
        float4 v = *(const float4*)(x + cI * 4);
        __half2 f01 = __floats2half2_rn(v.x, v.y);
        __half2 f23 = __floats2half2_rn(v.z, v.w);
        uint2 pk;
        pk.x = *(unsigned*)&f01;
        pk.y = *(unsigned*)&f23;
        *(uint2*)(g_x16 + cI * 4) = pk;
    }
}

// ---------------- CSR build ------------------------------------------------------
__global__ void hist_kernel(const void* __restrict__ eidx) {
    int e = blockIdx.x * blockDim.x + threadIdx.x;
    if (e < NE) atomicAdd(&g_deg[load_idx(eidx, (long long)NE + e)], 1);
}

__global__ void scanA_kernel() {
    __shared__ int warp_sums[32];
    int b = blockIdx.x, t = threadIdx.x;
    int i = b * 1024 + t;
    int lane = t & 31, w = t >> 5;
    int v = (i < NN) ? g_deg[i] : 0;
    int s = v;
#pragma unroll
    for (int off = 1; off < 32; off <<= 1) {
        int n = __shfl_up_sync(0xFFFFFFFFu, s, off);
        if (lane >= off) s += n;
    }
    if (lane == 31) warp_sums[w] = s;
    __syncthreads();
    if (w == 0) {
        int ws = warp_sums[lane];
#pragma unroll
        for (int off = 1; off < 32; off <<= 1) {
            int n = __shfl_up_sync(0xFFFFFFFFu, ws, off);
            if (lane >= off) ws += n;
        }
        warp_sums[lane] = ws;
    }
    __syncthreads();
    int woff = (w == 0) ? 0 : warp_sums[w - 1];
    int incl = s + woff;
    if (i < NN) g_rowptr[i] = incl - v;
    if (t == 1023) g_bsum[b] = incl;
}

__global__ void scanB_kernel(int nblocks) {
    __shared__ int sh[64];
    int t = threadIdx.x;
    int v = (t < nblocks) ? g_bsum[t] : 0;
    sh[t] = v;
    __syncthreads();
    for (int off = 1; off < 64; off <<= 1) {
        int n = (t >= off) ? sh[t - off] : 0;
        __syncthreads();
        sh[t] += n;
        __syncthreads();
    }
    g_boff[t] = sh[t] - v;
    if (t == 0) g_rowptr[NN] = NE;
}

__global__ void scatter_kernel(const void* __restrict__ eidx) {
    int e = blockIdx.x * blockDim.x + threadIdx.x;
    if (e < NE) {
        int d = load_idx(eidx, (long long)NE + e);
        int pos = rp(d) + atomicAdd(&g_cursor[d], 1);
        if (pos >= 0 && pos < NE) g_csrc[pos] = load_idx(eidx, e);
    }
}

// ---------------- segment mean: warp per node, x4-unrolled fp16 gather -----------
template <int WHICH>   // 0: gather g_x16, 1: gather g_h1h16
__global__ void aggregate_kernel() {
    const __half* __restrict__ p = (WHICH == 0) ? g_x16 : g_h1h16;
    int gw   = (blockIdx.x * blockDim.x + threadIdx.x) >> 5;
    int lane = threadIdx.x & 31;
    if (gw >= NN) return;
    int r0 = rp(gw);
    int r1 = rp(gw + 1);
    float4 acc = make_float4(0.f, 0.f, 0.f, 0.f);
    int i = r0;
    for (; i + 4 <= r1; i += 4) {
        int s0 = g_csrc[i + 0], s1 = g_csrc[i + 1];
        int s2 = g_csrc[i + 2], s3 = g_csrc[i + 3];
        uint2 v0 = *(const uint2*)(p + (size_t)s0 * F + lane * 4);
        uint2 v1 = *(const uint2*)(p + (size_t)s1 * F + lane * 4);
        uint2 v2 = *(const uint2*)(p + (size_t)s2 * F + lane * 4);
        uint2 v3 = *(const uint2*)(p + (size_t)s3 * F + lane * 4);
        float2 a, b;
        a = __half22float2(*(__half2*)&v0.x); b = __half22float2(*(__half2*)&v0.y);
        acc.x += a.x; acc.y += a.y; acc.z += b.x; acc.w += b.y;
        a = __half22float2(*(__half2*)&v1.x); b = __half22float2(*(__half2*)&v1.y);
        acc.x += a.x; acc.y += a.y; acc.z += b.x; acc.w += b.y;
        a = __half22float2(*(__half2*)&v2.x); b = __half22float2(*(__half2*)&v2.y);
        acc.x += a.x; acc.y += a.y; acc.z += b.x; acc.w += b.y;
        a = __half22float2(*(__half2*)&v3.x); b = __half22float2(*(__half2*)&v3.y);
        acc.x += a.x; acc.y += a.y; acc.z += b.x; acc.w += b.y;
    }
    for (; i < r1; i++) {
        int s = g_csrc[i];
        uint2 v = *(const uint2*)(p + (size_t)s * F + lane * 4);
        float2 a = __half22float2(*(__half2*)&v.x);
        float2 b = __half22float2(*(__half2*)&v.y);
        acc.x += a.x; acc.y += a.y; acc.z += b.x; acc.w += b.y;
    }
    float inv = 1.0f / (float)max(r1 - r0, 1);
    __half2 m01 = __floats2half2_rn(acc.x * inv, acc.y * inv);
    __half2 m23 = __floats2half2_rn(acc.z * inv, acc.w * inv);
    uint2 pk;
    pk.x = *(unsigned*)&m01;
    pk.y = *(unsigned*)&m23;
    *(uint2*)(g_m16 + (size_t)gw * F + lane * 4) = pk;
}

// ---------------- HMMA fp16 GEMM (A exact fp16, W split fp16 hi/lo) ---------------
// MODE 0: h1 = relu(mean@W1 + x@W1r + b)  -> g_h1h16 fp16, K=256
// MODE 1: h2 = mean@W2 + h1@W2r + b       -> g_h2h16 fp16, K=256
// MODE 2: ABh[:, by*128..] = h2 @ wtc_by  -> g_ABh fp16, K=128, grid.y=2
#define SAPAD 40

template <int MODE>
__global__ __launch_bounds__(512)
void mma_gemm(const float* __restrict__ bias, int M)
{
    constexpr int NCHUNK = (MODE <= 1) ? 8 : 4;   // K-chunks of 32
    constexpr int KTOT   = (MODE <= 1) ? 256 : 128;
    const int wtoff = (MODE == 0) ? 0 : (MODE == 1) ? 32768
                     : 65536 + (int)blockIdx.y * 16384;

    __shared__ __half sA[128][SAPAD];
    __shared__ __half sWh[128][SAPAD], sWl[128][SAPAD];

    int tid  = threadIdx.x;
    int wid  = tid >> 5, lane = tid & 31;
    int m0   = blockIdx.x * 128;
    int wm   = wid >> 2, wn = wid & 3;
    int mb   = wm * 32,  nb = wn * 32;

    float acc[2][4][4];
#pragma unroll
    for (int mi = 0; mi < 2; mi++)
#pragma unroll
        for (int ni = 0; ni < 4; ni++)
#pragma unroll
            for (int q = 0; q < 4; q++) acc[mi][ni][q] = 0.f;

    const int frow = tid >> 2;            // 0..127
    const int fseg = (tid & 3) * 8;       // 0,8,16,24 (elems)
    const int gmf  = m0 + frow;

    const int a_r = (lane & 15);
    const int a_c = (lane >> 4) * 8;
    const int b_r = (lane & 7);
    const int b_c = ((lane >> 3) & 1) * 8;

    for (int ch = 0; ch < NCHUNK; ch++) {
        const __half* a16;
        int kk0;
        if (MODE == 2)      { a16 = g_h2h16; kk0 = ch * 32; }
        else if (ch < 4)    { a16 = g_m16;   kk0 = ch * 32; }
        else if (MODE == 0) { a16 = g_x16;   kk0 = (ch - 4) * 32; }
        else                { a16 = g_h1h16; kk0 = (ch - 4) * 32; }
        int kkw = ch * 32;

        {
            uint4 va = make_uint4(0, 0, 0, 0);
            if (gmf < M) va = *(const uint4*)(a16 + (size_t)gmf * F + kk0 + fseg);
            *(uint4*)&sA[frow][fseg] = va;
            *(uint4*)&sWh[frow][fseg] =
                *(const uint4*)(g_wt_hi + wtoff + (size_t)frow * KTOT + kkw + fseg);
            *(uint4*)&sWl[frow][fseg] =
                *(const uint4*)(g_wt_lo + wtoff + (size_t)frow * KTOT + kkw + fseg);
        }
        __syncthreads();

#pragma unroll
        for (int ks = 0; ks < 2; ks++) {
            uint32_t af[2][4], whf[4][2], wlf[4][2];
#pragma unroll
            for (int mi = 0; mi < 2; mi++)
                ldm_x4(af[mi], sm32(&sA[mb + mi * 16 + a_r][ks * 16 + a_c]));
#pragma unroll
            for (int ni = 0; ni < 4; ni++) {
                ldm_x2(whf[ni], sm32(&sWh[nb + ni * 8 + b_r][ks * 16 + b_c]));
                ldm_x2(wlf[ni], sm32(&sWl[nb + ni * 8 + b_r][ks * 16 + b_c]));
            }
#pragma unroll
            for (int mi = 0; mi < 2; mi++)
#pragma unroll
                for (int ni = 0; ni < 4; ni++) {
                    mma16816h(acc[mi][ni], af[mi], whf[ni]);
                    mma16816h(acc[mi][ni], af[mi], wlf[ni]);
                }
        }
        __syncthreads();
    }

    const int trow = lane >> 2;
    const int tcol = (lane & 3) * 2;
#pragma unroll
    for (int mi = 0; mi < 2; mi++) {
#pragma unroll
        for (int half = 0; half < 2; half++) {
            int m = m0 + mb + mi * 16 + trow + half * 8;
            if (m >= M) continue;
#pragma unroll
            for (int ni = 0; ni < 4; ni++) {
                int col = nb + ni * 8 + tcol;
                float vx = acc[mi][ni][half * 2 + 0];
                float vy = acc[mi][ni][half * 2 + 1];
                if (MODE <= 1) { vx += bias[col]; vy += bias[col + 1]; }
                if (MODE == 0) { vx = fmaxf(vx, 0.f); vy = fmaxf(vy, 0.f); }
                __half2 h = __floats2half2_rn(vx, vy);
                if (MODE == 0) {
                    *(__half2*)(g_h1h16 + (size_t)m * F + col) = h;
                } else if (MODE == 1) {
                    *(__half2*)(g_h2h16 + (size_t)m * F + col) = h;
                } else {
                    *(__half2*)(g_ABh + (size_t)m * 256 + blockIdx.y * 128 + col) = h;
                }
            }
        }
    }
}

// ---------------- edge classifier: warp per edge (fp16 AB table) -----------------
__global__ __launch_bounds__(256)
void edge_kernel(const void* __restrict__ eidx,
                 const float* __restrict__ ea,
                 const float* __restrict__ Wc1,
                 const float* __restrict__ bc1,
                 const float* __restrict__ Wc2,
                 const float* __restrict__ bc2,
                 float* __restrict__ out)
{
    __shared__ float sWe0[128], sWe1[128], sWe2[128], sb[128], sw2[128];
    int tid = threadIdx.x;
    if (tid < 128) {
        sWe0[tid] = Wc1[256 * 128 + tid];
        sWe1[tid] = Wc1[257 * 128 + tid];
        sWe2[tid] = Wc1[258 * 128 + tid];
        sb[tid]   = bc1[tid];
        sw2[tid]  = Wc2[tid];
    }
    __syncthreads();

    int e = blockIdx.x * (blockDim.x >> 5) + (tid >> 5);
    if (e >= NE) return;
    int lane = tid & 31;
    int j = lane * 4;

    int s = load_idx(eidx, e);
    int d = load_idx(eidx, (long long)NE + e);

    uint2 av = *(const uint2*)(g_ABh + (size_t)s * 256 + j);
    uint2 bv = *(const uint2*)(g_ABh + (size_t)d * 256 + 128 + j);
    float2 a01 = __half22float2(*(__half2*)&av.x);
    float2 a23 = __half22float2(*(__half2*)&av.y);
    float2 b01 = __half22float2(*(__half2*)&bv.x);
    float2 b23 = __half22float2(*(__half2*)&bv.y);

    float4 w0 = *(const float4*)&sWe0[j];
    float4 w1 = *(const float4*)&sWe1[j];
    float4 w2 = *(const float4*)&sWe2[j];
    float4 bb = *(const float4*)&sb[j];
    float4 wc = *(const float4*)&sw2[j];

    float e0 = ea[(size_t)e * 3 + 0];
    float e1 = ea[(size_t)e * 3 + 1];
    float e2 = ea[(size_t)e * 3 + 2];

    float h, acc = 0.f;
    h = a01.x + b01.x + e0 * w0.x + e1 * w1.x + e2 * w2.x + bb.x;
    acc += fmaxf(h, 0.f) * wc.x;
    h = a01.y + b01.y + e0 * w0.y + e1 * w1.y + e2 * w2.y + bb.y;
    acc += fmaxf(h, 0.f) * wc.y;
    h = a23.x + b23.x + e0 * w0.z + e1 * w1.z + e2 * w2.z + bb.z;
    acc += fmaxf(h, 0.f) * wc.z;
    h = a23.y + b23.y + e0 * w0.w + e1 * w1.w + e2 * w2.w + bb.w;
    acc += fmaxf(h, 0.f) * wc.w;

#pragma unroll
    for (int off = 16; off > 0; off >>= 1)
        acc += __shfl_xor_sync(0xFFFFFFFFu, acc, off);

    if (lane == 0) out[e] = acc + bc2[0];
}

// ---------------- launch -----------------------------------------------------------
extern "C" void kernel_launch(void* const* d_in, const int* in_sizes, int n_in,
                              void* d_out, int out_size)
{
    const float* x    = (const float*)d_in[0];
    const void*  eidx = d_in[1];
    const float* ea   = (const float*)d_in[2];
    const float* W1l  = (const float*)d_in[3];
    const float* b1l  = (const float*)d_in[4];
    const float* W1r  = (const float*)d_in[5];
    const float* W2l  = (const float*)d_in[6];
    const float* b2l  = (const float*)d_in[7];
    const float* W2r  = (const float*)d_in[8];
    const float* Wc1  = (const float*)d_in[9];
    const float* bc1  = (const float*)d_in[10];
    const float* Wc2  = (const float*)d_in[11];
    const float* bc2  = (const float*)d_in[12];
    float* out = (float*)d_out;

    const int SCAN_BLOCKS = (NN + 1023) / 1024;  // 49

    long long setup_threads = (long long)NN + 98304 + (long long)NN * 32;
    int setup_grid = (int)((setup_threads + 255) / 256);
    setup_kernel<<<setup_grid, 256>>>(eidx, x, W1l, W1r, W2l, W2r, Wc1);

    hist_kernel<<<(NE + 255) / 256, 256>>>(eidx);
    scanA_kernel<<<SCAN_BLOCKS, 1024>>>();
    scanB_kernel<<<1, 64>>>(SCAN_BLOCKS);
    scatter_kernel<<<(NE + 255) / 256, 256>>>(eidx);

    const int aggGrid  = (NN * 32 + 255) / 256;
    const int gemmGrid = (NN + 127) / 128;       // 391

    aggregate_kernel<0><<<aggGrid, 256>>>();
    mma_gemm<0><<<gemmGrid, 512>>>(b1l, NN);

    aggregate_kernel<1><<<aggGrid, 256>>>();
    mma_gemm<1><<<gemmGrid, 512>>>(b2l, NN);

    mma_gemm<2><<<dim3(gemmGrid, 2), 512>>>(nullptr, NN);

    edge_kernel<<<(NE * 32 + 255) / 256, 256>>>(eidx, ea, Wc1, bc1, Wc2, bc2, out);
}